// round 3
// baseline (speedup 1.0000x reference)
#include <cuda_runtime.h>
#include <cstdint>

#define WD 128
#define HT 128
#define NB 8
#define NC 16
#define HW (HT*WD)
#define CHW (NC*HW)
#define HO 127
#define WO 127
#define CH_SPLIT 2
#define CH_PER (NC/CH_SPLIT)

typedef unsigned long long ull;

__device__ __forceinline__ ull pack2(float x, float y) {
    ull r; asm("mov.b64 %0, {%1, %2};" : "=l"(r) : "f"(x), "f"(y)); return r;
}
__device__ __forceinline__ void unpack2(float& x, float& y, ull v) {
    asm("mov.b64 {%0, %1}, %2;" : "=f"(x), "=f"(y) : "l"(v));
}
__device__ __forceinline__ ull fma2(ull a, ull b, ull c) {
    ull d; asm("fma.rn.f32x2 %0, %1, %2, %3;" : "=l"(d) : "l"(a), "l"(b), "l"(c)); return d;
}
__device__ __forceinline__ ull add2(ull a, ull b) {
    ull d; asm("add.rn.f32x2 %0, %1, %2;" : "=l"(d) : "l"(a), "l"(b)); return d;
}
__device__ __forceinline__ void lds_row(ull& lo, ull& hi, unsigned addr) {
    asm volatile("ld.shared.v2.u64 {%0, %1}, [%2];" : "=l"(lo), "=l"(hi) : "r"(addr));
}

// Power-basis coefficient table: for cell t (0..10), spline contribution per
// tap f is A + B*u + C*u^2 + D*u^3.  Row layout (per-lane replicated):
//   tab[((t*4 + k)*32 + lane)] : float4 over taps f=0..3, k in {A,B,C,D}.
// Cell 11 = all-zero (out-of-range inputs).
#define NCELLS 12

__global__ void __launch_bounds__(256) kan_scatter_kernel(
    const float* __restrict__ x,
    const float* __restrict__ base_weight,
    const float* __restrict__ spline_weight,
    const float* __restrict__ spline_scaler,
    const float* __restrict__ grid,
    float* __restrict__ out)
{
    __shared__ float4 tab[NCELLS * 4 * 32];

    const int tid = threadIdx.x;

    // ── Build the power-basis table ──
    for (int e = tid; e < NCELLS * 4 * 32; e += 256) {
        const int k = (e >> 5) & 3;   // power index
        const int t = e >> 7;         // cell
        float4 val = make_float4(0.f, 0.f, 0.f, 0.f);
        if (t <= 10) {
            float o[4];
#pragma unroll
            for (int f = 0; f < 4; f++) {
                const float sc = spline_scaler[f];
                float c[4];
#pragma unroll
                for (int j = 0; j < 4; j++) {
                    const int idx = t - 3 + j;   // basis index
                    c[j] = (idx >= 0 && idx < 8)
                         ? spline_weight[f * 8 + idx] * sc : 0.f;
                }
                float r;
                if (k == 0)      r = (c[0] + 4.f * c[1] + c[2]) * (1.f / 6.f);
                else if (k == 1) r = (c[2] - c[0]) * 0.5f;
                else if (k == 2) r = (c[0] - 2.f * c[1] + c[2]) * 0.5f;
                else             r = (3.f * (c[1] - c[2]) + c[3] - c[0]) * (1.f / 6.f);
                o[f] = r;
            }
            val = make_float4(o[0], o[1], o[2], o[3]);
        }
        tab[e] = val;
    }
    __syncthreads();

    const float bw0 = __ldg(base_weight + 0);
    const float bw1 = __ldg(base_weight + 1);
    const float bw2 = __ldg(base_weight + 2);
    const float bw3 = __ldg(base_weight + 3);
    const float g0   = __ldg(grid + 0);
    const float invh = 1.0f / (__ldg(grid + 1) - g0);
    const float off0 = -g0 * invh;

    const ull bw01 = pack2(bw0, bw1);
    const ull bw23 = pack2(bw2, bw3);

    const int n = blockIdx.x * 256 + tid;     // pixel id (b,i,j)
    const int j = n & (WD - 1);
    const int i = (n >> 7) & (HT - 1);
    const int b = n >> 14;
    const int ch0 = blockIdx.y * CH_PER;

    const unsigned tab_base =
        (unsigned)__cvta_generic_to_shared(tab) + (unsigned)((tid & 31) * 16);

    const float* xp = x + b * CHW + ch0 * HW + i * WD + j;

    ull acc01 = 0ull, acc23 = 0ull;

#pragma unroll
    for (int ch = 0; ch < CH_PER; ch++) {
        const float v  = __ldg(xp + ch * HW);
        const float pp = fmaf(v, invh, off0);
        const float fc = floorf(pp);
        const float u  = pp - fc;
        const int cell = (int)fc;
        const int cb   = ((unsigned)cell <= 10u) ? cell : 11;

        const unsigned a = tab_base + ((unsigned)cb << 11);
        ull A01, A23, B01, B23, C01, C23, D01, D23;
        lds_row(A01, A23, a);
        lds_row(B01, B23, a + 512);
        lds_row(C01, C23, a + 1024);
        lds_row(D01, D23, a + 1536);

        const ull u2 = pack2(u, u);
        const ull t01 = fma2(fma2(fma2(D01, u2, C01), u2, B01), u2, A01);
        const ull t23 = fma2(fma2(fma2(D23, u2, C23), u2, B23), u2, A23);

        // SiLU base path
        const float s  = v * __frcp_rn(1.f + __expf(-v));
        const ull s2 = pack2(s, s);
        acc01 = fma2(s2, bw01, acc01);
        acc23 = fma2(s2, bw23, acc23);
        acc01 = add2(acc01, t01);
        acc23 = add2(acc23, t23);
    }

    float a0, a1, a2, a3;
    unpack2(a0, a1, acc01);
    unpack2(a2, a3, acc23);

    // Scatter: tap f=(di,dj) of pixel (i,j) contributes to out(i-di, j-dj).
    float* ob = out + b * (HO * WO);
    if (i < HO) {
        if (j < WO) atomicAdd(ob + i * WO + j,      a0);
        if (j >= 1) atomicAdd(ob + i * WO + (j-1),  a1);
    }
    if (i >= 1) {
        if (j < WO) atomicAdd(ob + (i-1) * WO + j,     a2);
        if (j >= 1) atomicAdd(ob + (i-1) * WO + (j-1), a3);
    }
}

extern "C" void kernel_launch(void* const* d_in, const int* in_sizes, int n_in,
                              void* d_out, int out_size)
{
    const float* x  = (const float*)d_in[0];
    const float* bw = (const float*)d_in[1];
    const float* sw = (const float*)d_in[2];
    const float* ss = (const float*)d_in[3];
    const float* gr = (const float*)d_in[4];
    float* out = (float*)d_out;

    (void)in_sizes; (void)n_in;

    cudaMemsetAsync(out, 0, (size_t)out_size * sizeof(float));

    dim3 gs((NB * HT * WD) / 256, CH_SPLIT, 1);
    kan_scatter_kernel<<<gs, 256>>>(x, bw, sw, ss, gr, out);
}

// round 4
// speedup vs baseline: 1.1345x; 1.1345x over previous
#include <cuda_runtime.h>
#include <cstdint>

#define WD 128
#define HT 128
#define NB 8
#define NC 16
#define HW (HT*WD)
#define CHW (NC*HW)
#define HO 127
#define WO 127
#define NCELLS 12

typedef unsigned long long ull;

// 4 pre-shifted tap planes, SoA. 4*8*128*128*4B = 8 MB scratch.
__device__ float g_Y[4][NB][HT][WD];

__device__ __forceinline__ ull pack2(float x, float y) {
    ull r; asm("mov.b64 %0, {%1, %2};" : "=l"(r) : "f"(x), "f"(y)); return r;
}
__device__ __forceinline__ void unpack2(float& x, float& y, ull v) {
    asm("mov.b64 {%0, %1}, %2;" : "=f"(x), "=f"(y) : "l"(v));
}
__device__ __forceinline__ ull fma2(ull a, ull b, ull c) {
    ull d; asm("fma.rn.f32x2 %0, %1, %2, %3;" : "=l"(d) : "l"(a), "l"(b), "l"(c)); return d;
}
__device__ __forceinline__ ull add2(ull a, ull b) {
    ull d; asm("add.rn.f32x2 %0, %1, %2;" : "=l"(d) : "l"(a), "l"(b)); return d;
}
__device__ __forceinline__ void lds_row(ull& lo, ull& hi, unsigned addr) {
    asm volatile("ld.shared.v2.u64 {%0, %1}, [%2];" : "=l"(lo), "=l"(hi) : "r"(addr));
}

__global__ void __launch_bounds__(256) kan_eval_kernel(
    const float* __restrict__ x,
    const float* __restrict__ base_weight,
    const float* __restrict__ spline_weight,
    const float* __restrict__ spline_scaler,
    const float* __restrict__ grid)
{
    // Power-basis table: cell t (0..10): spline(u) = A + B u + C u^2 + D u^3
    // per tap. tab[((t*4+k)*32 + lane)] = float4 over taps. Cell 11 = zeros.
    __shared__ float4 tab[NCELLS * 4 * 32];

    const int tid = threadIdx.x;

    for (int e = tid; e < NCELLS * 4 * 32; e += 256) {
        const int k = (e >> 5) & 3;
        const int t = e >> 7;
        float4 val = make_float4(0.f, 0.f, 0.f, 0.f);
        if (t <= 10) {
            float o[4];
#pragma unroll
            for (int f = 0; f < 4; f++) {
                const float sc = spline_scaler[f];
                float c[4];
#pragma unroll
                for (int jj = 0; jj < 4; jj++) {
                    const int idx = t - 3 + jj;
                    c[jj] = (idx >= 0 && idx < 8)
                          ? spline_weight[f * 8 + idx] * sc : 0.f;
                }
                float r;
                if (k == 0)      r = (c[0] + 4.f * c[1] + c[2]) * (1.f / 6.f);
                else if (k == 1) r = (c[2] - c[0]) * 0.5f;
                else if (k == 2) r = (c[0] - 2.f * c[1] + c[2]) * 0.5f;
                else             r = (3.f * (c[1] - c[2]) + c[3] - c[0]) * (1.f / 6.f);
                o[f] = r;
            }
            val = make_float4(o[0], o[1], o[2], o[3]);
        }
        tab[e] = val;
    }
    __syncthreads();

    const float bw0 = __ldg(base_weight + 0);
    const float bw1 = __ldg(base_weight + 1);
    const float bw2 = __ldg(base_weight + 2);
    const float bw3 = __ldg(base_weight + 3);
    const float g0   = __ldg(grid + 0);
    const float invh = 1.0f / (__ldg(grid + 1) - g0);
    const float off0 = -g0 * invh;

    const ull bw01 = pack2(bw0, bw1);
    const ull bw23 = pack2(bw2, bw3);

    const int n = blockIdx.x * 256 + tid;
    const int j = n & (WD - 1);
    const int i = (n >> 7) & (HT - 1);
    const int b = n >> 14;

    const unsigned tab_base =
        (unsigned)__cvta_generic_to_shared(tab) + (unsigned)((tid & 31) * 16);

    const float* xp = x + b * CHW + i * WD + j;

    ull acc01 = 0ull, acc23 = 0ull;

#pragma unroll
    for (int ch = 0; ch < NC; ch++) {
        const float v  = __ldg(xp + ch * HW);
        const float pp = fmaf(v, invh, off0);
        const float fc = floorf(pp);
        const float u  = pp - fc;
        const int cell = (int)fc;
        const int cb   = ((unsigned)cell <= 10u) ? cell : 11;

        const unsigned a = tab_base + ((unsigned)cb << 11);
        ull A01, A23, B01, B23, C01, C23, D01, D23;
        lds_row(A01, A23, a);
        lds_row(B01, B23, a + 512);
        lds_row(C01, C23, a + 1024);
        lds_row(D01, D23, a + 1536);

        const ull u2 = pack2(u, u);
        const ull t01 = fma2(fma2(fma2(D01, u2, C01), u2, B01), u2, A01);
        const ull t23 = fma2(fma2(fma2(D23, u2, C23), u2, B23), u2, A23);

        const float s = v * __frcp_rn(1.f + __expf(-v));
        const ull s2 = pack2(s, s);
        acc01 = fma2(s2, bw01, acc01);
        acc23 = fma2(s2, bw23, acc23);
        acc01 = add2(acc01, t01);
        acc23 = add2(acc23, t23);
    }

    float a0, a1, a2, a3;
    unpack2(a0, a1, acc01);
    unpack2(a2, a3, acc23);

    // Pre-shifted stores: combine becomes an aligned elementwise 4-plane add.
    // Wrapped slots (row/col 127 of the shifted planes) are never read.
    const int base = b * HW;
    const int jm = (j - 1) & (WD - 1);
    const int im = (i - 1) & (HT - 1);
    (&g_Y[0][0][0][0])[base + i  * WD + j ] = a0;
    (&g_Y[1][0][0][0])[base + i  * WD + jm] = a1;
    (&g_Y[2][0][0][0])[base + im * WD + j ] = a2;
    (&g_Y[3][0][0][0])[base + im * WD + jm] = a3;
}

// One thread per 4-column group: 8b * 127r * 32grp = 32512 threads = 127 blocks.
__global__ void __launch_bounds__(256) kan_combine_kernel(float* __restrict__ out)
{
    const int t  = blockIdx.x * 256 + threadIdx.x;
    const int cg = t & 31;
    const int rb = t >> 5;
    const int r  = rb % HO;
    const int b  = rb / HO;
    const int c  = cg * 4;

    const int m = b * HW + r * WD + c;
    const float4 p0 = *(const float4*)(&g_Y[0][0][0][0] + m);
    const float4 p1 = *(const float4*)(&g_Y[1][0][0][0] + m);
    const float4 p2 = *(const float4*)(&g_Y[2][0][0][0] + m);
    const float4 p3 = *(const float4*)(&g_Y[3][0][0][0] + m);

    float* ob = out + (b * HO + r) * WO + c;
    ob[0] = p0.x + p1.x + p2.x + p3.x;
    ob[1] = p0.y + p1.y + p2.y + p3.y;
    ob[2] = p0.z + p1.z + p2.z + p3.z;
    if (c + 3 < WO)
        ob[3] = p0.w + p1.w + p2.w + p3.w;
}

extern "C" void kernel_launch(void* const* d_in, const int* in_sizes, int n_in,
                              void* d_out, int out_size)
{
    const float* x  = (const float*)d_in[0];
    const float* bw = (const float*)d_in[1];
    const float* sw = (const float*)d_in[2];
    const float* ss = (const float*)d_in[3];
    const float* gr = (const float*)d_in[4];
    float* out = (float*)d_out;

    (void)in_sizes; (void)n_in; (void)out_size;

    kan_eval_kernel<<<(NB * HT * WD) / 256, 256>>>(x, bw, sw, ss, gr);
    kan_combine_kernel<<<(NB * HO * 32) / 256, 256>>>(out);
}

// round 5
// speedup vs baseline: 1.2799x; 1.1282x over previous
#include <cuda_runtime.h>
#include <cstdint>

#define WD 128
#define HT 128
#define NB 8
#define NC 16
#define HW (HT*WD)
#define CHW (NC*HW)
#define HO 127
#define WO 127
#define TR 8            // output rows per strip
#define NSTRIP 16
#define CSPLIT 4
#define CPER (NC/CSPLIT)
#define NCELLS 12

typedef unsigned long long ull;

__device__ __forceinline__ ull pack2(float x, float y) {
    ull r; asm("mov.b64 %0, {%1, %2};" : "=l"(r) : "f"(x), "f"(y)); return r;
}
__device__ __forceinline__ void unpack2(float& x, float& y, ull v) {
    asm("mov.b64 {%0, %1}, %2;" : "=f"(x), "=f"(y) : "l"(v));
}
__device__ __forceinline__ ull fma2(ull a, ull b, ull c) {
    ull d; asm("fma.rn.f32x2 %0, %1, %2, %3;" : "=l"(d) : "l"(a), "l"(b), "l"(c)); return d;
}
__device__ __forceinline__ ull add2(ull a, ull b) {
    ull d; asm("add.rn.f32x2 %0, %1, %2;" : "=l"(d) : "l"(a), "l"(b)); return d;
}
__device__ __forceinline__ void lds_row(ull& lo, ull& hi, unsigned addr) {
    asm volatile("ld.shared.v2.u64 {%0, %1}, [%2];" : "=l"(lo), "=l"(hi) : "r"(addr));
}

__global__ void __launch_bounds__(256) kan_fused_kernel(
    const float* __restrict__ x,
    const float* __restrict__ base_weight,
    const float* __restrict__ spline_weight,
    const float* __restrict__ spline_scaler,
    const float* __restrict__ grid,
    float* __restrict__ out)
{
    // Per-lane-replicated power-basis table: cell t (0..10):
    // spline(u) = A + B u + C u^2 + D u^3 per tap. Cell 11 = zeros.
    __shared__ float4 tab[NCELLS * 4 * 32];      // 24.5 KB
    __shared__ float4 staging[NCELLS * 4];
    // Tap planes for this strip's 9 eval rows.
    __shared__ float sa0[TR + 1][WD];
    __shared__ float sa1[TR + 1][WD];
    __shared__ float sa2[TR + 1][WD];
    __shared__ float sa3[TR + 1][WD];

    const int tid = threadIdx.x;

    // ── Stage 1: compute 48 coefficient float4s once ──
    if (tid < NCELLS * 4) {
        const int t = tid >> 2;
        const int k = tid & 3;
        float4 val = make_float4(0.f, 0.f, 0.f, 0.f);
        if (t <= 10) {
            float o[4];
#pragma unroll
            for (int f = 0; f < 4; f++) {
                const float sc = spline_scaler[f];
                float c[4];
#pragma unroll
                for (int jj = 0; jj < 4; jj++) {
                    const int idx = t - 3 + jj;
                    c[jj] = (idx >= 0 && idx < 8)
                          ? spline_weight[f * 8 + idx] * sc : 0.f;
                }
                float r;
                if (k == 0)      r = (c[0] + 4.f * c[1] + c[2]) * (1.f / 6.f);
                else if (k == 1) r = (c[2] - c[0]) * 0.5f;
                else if (k == 2) r = (c[0] - 2.f * c[1] + c[2]) * 0.5f;
                else             r = (3.f * (c[1] - c[2]) + c[3] - c[0]) * (1.f / 6.f);
                o[f] = r;
            }
            val = make_float4(o[0], o[1], o[2], o[3]);
        }
        staging[tid] = val;
    }
    __syncthreads();
    // ── Stage 2: replicate across 32 lanes ──
#pragma unroll
    for (int e = tid; e < NCELLS * 4 * 32; e += 256)
        tab[e] = staging[e >> 5];
    __syncthreads();

    const float bw0 = __ldg(base_weight + 0);
    const float bw1 = __ldg(base_weight + 1);
    const float bw2 = __ldg(base_weight + 2);
    const float bw3 = __ldg(base_weight + 3);
    const float g0   = __ldg(grid + 0);
    const float invh = 1.0f / (__ldg(grid + 1) - g0);
    const float off0 = -g0 * invh;

    const ull bw01 = pack2(bw0, bw1);
    const ull bw23 = pack2(bw2, bw3);

    const int r0  = blockIdx.x * TR;
    const int b   = blockIdx.y;
    const int ch0 = blockIdx.z * CPER;

    const unsigned tab_base =
        (unsigned)__cvta_generic_to_shared(tab) + (unsigned)((tid & 31) * 16);

    // ── Eval: 9 rows x 128 cols, CPER channels summed ──
    for (int e = tid; e < (TR + 1) * WD; e += 256) {
        const int rl  = e >> 7;
        const int c   = e & (WD - 1);
        const int row = r0 + rl;

        ull acc01 = 0ull, acc23 = 0ull;
        if (row < HT) {
            const float* xp = x + b * CHW + ch0 * HW + row * WD + c;
            float v[CPER];
#pragma unroll
            for (int q = 0; q < CPER; q++)          // front-batched: MLP=CPER
                v[q] = __ldg(xp + q * HW);

#pragma unroll
            for (int q = 0; q < CPER; q++) {
                const float vv = v[q];
                const float pp = fmaf(vv, invh, off0);
                const float fc = floorf(pp);
                const float u  = pp - fc;
                const int cell = (int)fc;
                const int cb   = ((unsigned)cell <= 10u) ? cell : 11;

                const unsigned a = tab_base + ((unsigned)cb << 11);
                ull A01, A23, B01, B23, C01, C23, D01, D23;
                lds_row(A01, A23, a);
                lds_row(B01, B23, a + 512);
                lds_row(C01, C23, a + 1024);
                lds_row(D01, D23, a + 1536);

                const ull u2  = pack2(u, u);
                const ull t01 = fma2(fma2(fma2(D01, u2, C01), u2, B01), u2, A01);
                const ull t23 = fma2(fma2(fma2(D23, u2, C23), u2, B23), u2, A23);

                const float s = vv * __frcp_rn(1.f + __expf(-vv));
                const ull s2 = pack2(s, s);
                acc01 = fma2(s2, bw01, acc01);
                acc23 = fma2(s2, bw23, acc23);
                acc01 = add2(acc01, t01);
                acc23 = add2(acc23, t23);
            }
        }
        float a0, a1, a2, a3;
        unpack2(a0, a1, acc01);
        unpack2(a2, a3, acc23);
        sa0[rl][c] = a0;
        sa1[rl][c] = a1;
        sa2[rl][c] = a2;
        sa3[rl][c] = a3;
    }

    __syncthreads();

    // ── Combine from smem, scatter one atomic per output ──
#pragma unroll
    for (int o = tid; o < TR * WD; o += 256) {
        const int rl = o >> 7;
        const int c  = o & (WD - 1);
        const int r  = r0 + rl;
        if (r < HO && c < WO) {
            const float val = sa0[rl][c] + sa1[rl][c + 1] +
                              sa2[rl + 1][c] + sa3[rl + 1][c + 1];
            atomicAdd(out + (b * HO + r) * WO + c, val);
        }
    }
}

extern "C" void kernel_launch(void* const* d_in, const int* in_sizes, int n_in,
                              void* d_out, int out_size)
{
    const float* x  = (const float*)d_in[0];
    const float* bw = (const float*)d_in[1];
    const float* sw = (const float*)d_in[2];
    const float* ss = (const float*)d_in[3];
    const float* gr = (const float*)d_in[4];
    float* out = (float*)d_out;

    (void)in_sizes; (void)n_in;

    cudaMemsetAsync(out, 0, (size_t)out_size * sizeof(float));

    dim3 gs(NSTRIP, NB, CSPLIT);   // 16 x 8 x 4 = 512 blocks
    kan_fused_kernel<<<gs, 256>>>(x, bw, sw, ss, gr, out);
}